// round 11
// baseline (speedup 1.0000x reference)
#include <cuda_runtime.h>
#include <cuda_bf16.h>

#define BB 2
#define H 256
#define W 832
#define NPIX (H*W)

#define TS 32
#define HALO 10
#define TY_N (H/TS)          // 8
#define TX_N (W/TS)          // 26
#define NTILE (TY_N*TX_N)    // 208 per batch
#define TCAP 352             // >= 18*18 = 324 (kept points pairwise Chebyshev >= 3 in 52x52 halo)
#define PTMAX 24576          // >= ceil(256/3)*ceil(832/3) worst-case kept points per batch

// kept-point list (k_scan writes, k_search reads, k_diffuse resets count)
__device__ int    g_kcnt[BB];
__device__ int    g_kpos[BB*PTMAX];          // (i<<16)|j
// per-tile binned active-point lists (k_search writes, k_diffuse reads+resets)
__device__ int    g_tcnt[BB*NTILE];
__device__ int    g_tpos[BB*NTILE*TCAP];     // (i<<16)|j
__device__ float2 g_tdxy[BB*NTILE*TCAP];
__device__ float  g_wk[441];                 // weight LUT, written by k_search block (0,0)

__global__ void k_nop() {}

// on-demand orientation: circular 3x3 box blur + edge-clamped np.gradient -> (cos, sin) of atan2
__device__ __forceinline__ void orient(const float* __restrict__ m, int i, int j,
                                       float& cs, float& ss) {
    float patch[5][5];
#pragma unroll
    for (int r = 0; r < 5; r++) {
        int ii = i + r - 2; ii += (ii < 0) ? H : 0; ii -= (ii >= H) ? H : 0;
#pragma unroll
        for (int c = 0; c < 5; c++) {
            int jj = j + c - 2; jj += (jj < 0) ? W : 0; jj -= (jj >= W) ? W : 0;
            patch[r][c] = m[ii*W + jj];
        }
    }
#define BLUR_AT(di, dj) (patch[1+di][1+dj] + patch[1+di][2+dj] + patch[1+di][3+dj] \
                       + patch[2+di][1+dj] + patch[2+di][2+dj] + patch[2+di][3+dj] \
                       + patch[3+di][1+dj] + patch[3+di][2+dj] + patch[3+di][3+dj])
    float byp = BLUR_AT(1, 0), bym = BLUR_AT(-1, 0), bc = BLUR_AT(0, 0);
    float bxp = BLUR_AT(0, 1), bxm = BLUR_AT(0, -1);
#undef BLUR_AT
    float gyv = (i == 0) ? (byp - bc) : (i == H-1) ? (bc - bym) : 0.5f * (byp - bym);
    float gxv = (j == 0) ? (bxp - bc) : (j == W-1) ? (bc - bxm) : 0.5f * (bxp - bxm);
    float r = sqrtf(gxv*gxv + gyv*gyv);
    if (r > 0.f) { cs = gxv / r; ss = gyv / r; }
    else         { cs = 1.f;     ss = 0.f;     }   // atan2(0,0)=0
}

// ---------------- K1: dense sparsify -> global kept-point list ----------------
__global__ void __launch_bounds__(256) k_scan(const float* __restrict__ src) {
    int b = blockIdx.y;
    int p = blockIdx.x * 256 + threadIdx.x;
    const float* S = src + b*NPIX;
    if (S[p] > 0.5f) {
        int i = p / W, j = p - (p / W) * W;
        bool kept = true;
#pragma unroll
        for (int a = -2; a <= 2; a++) {
            int ii = i + a;
            if (ii < 0 || ii >= H) continue;
#pragma unroll
            for (int c = -2; c <= 2; c++) {
                int jj = j + c;
                if (jj < 0 || jj >= W) continue;
                int q = ii*W + jj;
                if (q < p && S[q] > 0.5f) kept = false;
            }
        }
        if (kept) {
            int idx = atomicAdd(&g_kcnt[b], 1);
            if (idx < PTMAX) g_kpos[b*PTMAX + idx] = (i << 16) | j;
        }
    }
}

// ---------------- K2: warp per kept point; prefetched offset probes; tile binning ----------------
__global__ void __launch_bounds__(256) k_search(const float* __restrict__ src,
                                                const float* __restrict__ dst,
                                                const int* __restrict__ xx,
                                                const int* __restrict__ yy, int K) {
    __shared__ int s_xx[128], s_yy[128];

    int b = blockIdx.y;
    int tid = threadIdx.x;
    int lane = tid & 31;
    int wg = blockIdx.x * 8 + (tid >> 5);   // global warp id within batch: 0..415
    const float* S = src + b*NPIX;
    const float* D = dst + b*NPIX;

    // LUT fill once per launch (input-independent, deterministic)
    if (blockIdx.x == 0 && b == 0) {
        for (int h = tid; h < 441; h += 256) {
            int dy = h / 21 - 10, dx = h % 21 - 10;
            g_wk[h] = expf(-sqrtf((float)(dx*dx + dy*dy)) * 0.2f);
        }
    }
    if (tid < K) { s_xx[tid] = xx[tid]; s_yy[tid] = yy[tid]; }
    __syncthreads();

    int cnt = min(g_kcnt[b], PTMAX);
    for (int pt = wg; pt < cnt; pt += 416) {
        int pp = g_kpos[b*PTMAX + pt];
        int pi = pp >> 16, pj = pp & 0xffff;
        float cs, ssv;
        orient(S, pi, pj, cs, ssv);   // warp-uniform broadcast loads

        // prefetch all 4 strided probes (independent loads -> 1 latency, not 4)
        bool inb[4]; int qv[4]; float dv[4];
#pragma unroll
        for (int u = 0; u < 4; u++) {
            int k = lane + u*32;
            inb[u] = false; dv[u] = 0.f; qv[u] = 0;
            if (k < K) {
                int ii = pi + s_yy[k], jj = pj + s_xx[k];
                if (ii >= 0 && ii < H && jj >= 0 && jj < W) { inb[u] = true; qv[u] = ii*W + jj; }
            }
        }
#pragma unroll
        for (int u = 0; u < 4; u++) if (inb[u]) dv[u] = D[qv[u]];

        float best = 1e9f; int bk = 0x7fffffff;
#pragma unroll
        for (int u = 0; u < 4; u++) {
            if (inb[u] && dv[u] > 0.5f) {
                int k = lane + u*32;
                int ii = pi + s_yy[k], jj = pj + s_xx[k];
                float cd, sd;
                orient(D, ii, jj, cd, sd);   // rare (~2 hits/point over whole warp)
                float ang = 1.0f - (cs*cd + ssv*sd);
                int ox = s_xx[k], oy = s_yy[k];
                float sc = 20.0f * sqrtf((float)(ox*ox + oy*oy)) + 10.5f * ang;
                if (sc < best) { best = sc; bk = k; }   // ascending k within lane
            }
        }
        // warp lexicographic (score, k) min -> global first-index-of-min (argmin semantics)
#pragma unroll
        for (int o = 16; o; o >>= 1) {
            float s2 = __shfl_xor_sync(0xffffffffu, best, o);
            int   k2 = __shfl_xor_sync(0xffffffffu, bk, o);
            if (s2 < best || (s2 == best && k2 < bk)) { best = s2; bk = k2; }
        }
        if (lane == 0 && best < 5e8f) {
            float2 dxy = make_float2((float)s_xx[bk], (float)s_yy[bk]);
            // bin into every 32x32 output tile whose 52x52 halo contains (pi,pj)
            int tylo = (pi <= 41) ? 0 : ((pi - 41 + 31) >> 5);
            int tyhi = min(TY_N - 1, (pi + 10) >> 5);
            int txlo = (pj <= 41) ? 0 : ((pj - 41 + 31) >> 5);
            int txhi = min(TX_N - 1, (pj + 10) >> 5);
            for (int ty = tylo; ty <= tyhi; ty++)
                for (int tx = txlo; tx <= txhi; tx++) {
                    int tile = (b * TY_N + ty) * TX_N + tx;
                    int idx = atomicAdd(&g_tcnt[tile], 1);
                    if (idx < TCAP) {
                        g_tpos[tile*TCAP + idx] = pp;
                        g_tdxy[tile*TCAP + idx] = dxy;
                    }
                }
        }
    }
}

// ---------------- K3: sparse diffusion; 4 rows per thread, warp-uniform row-band skip ----------------
__global__ void __launch_bounds__(256) k_diffuse(float* __restrict__ out) {
    __shared__ float  s_wk[441];
    __shared__ int    s_pos[TCAP];
    __shared__ float2 s_dxy[TCAP];

    int bb  = blockIdx.z;
    int tid = threadIdx.x;
    int tile = (bb * TY_N + blockIdx.y) * TX_N + blockIdx.x;

    // LUT from global (written by k_search) -- no MUFU here
    s_wk[tid] = g_wk[tid < 441 ? tid : 440];
    if (tid + 256 < 441) s_wk[tid + 256] = g_wk[tid + 256];

    int m = min(g_tcnt[tile], TCAP);
    for (int h = tid; h < m; h += 256) {
        s_pos[h] = g_tpos[tile*TCAP + h];
        s_dxy[h] = g_tdxy[tile*TCAP + h];
    }
    if (tid == 0) g_tcnt[tile] = 0;   // self-reset for next replay
    if (tid == 1 && blockIdx.x == 0 && blockIdx.y == 0) g_kcnt[bb] = 0;   // reset kept-count
    __syncthreads();

    int w = tid >> 5, lane = tid & 31;
    int ox = blockIdx.x * TS + lane;
    int ybase = blockIdx.y * TS + 4*w;   // this thread owns rows ybase..ybase+3, column ox

    float nx0=0.f,ny0=0.f,dn0=0.f, nx1=0.f,ny1=0.f,dn1=0.f;
    float nx2=0.f,ny2=0.f,dn2=0.f, nx3=0.f,ny3=0.f,dn3=0.f;

    for (int pI = 0; pI < m; pI++) {
        int pos = s_pos[pI];
        int dyb = (pos >> 16) - ybase + HALO;      // warp-uniform
        if ((unsigned)dyb > 23u) continue;         // uniform skip of ~55% of entries
        int ddx = (pos & 0xffff) - ox + HALO;
        if ((unsigned)ddx <= 20u) {
            float2 d = s_dxy[pI];
            int base = dyb * 21 + ddx;
            if ((unsigned) dyb      <= 20u) { float wv = s_wk[base];      nx0 += wv*d.x; ny0 += wv*d.y; dn0 += wv; }
            if ((unsigned)(dyb - 1) <= 20u) { float wv = s_wk[base - 21]; nx1 += wv*d.x; ny1 += wv*d.y; dn1 += wv; }
            if ((unsigned)(dyb - 2) <= 20u) { float wv = s_wk[base - 42]; nx2 += wv*d.x; ny2 += wv*d.y; dn2 += wv; }
            if ((unsigned)(dyb - 3) <= 20u) { float wv = s_wk[base - 63]; nx3 += wv*d.x; ny3 += wv*d.y; dn3 += wv; }
        }
    }

    float* outx = out + (bb*2 + 0)*NPIX;
    float* outy = out + (bb*2 + 1)*NPIX;
    int q = ybase * W + ox;
    float fx = (float)ox;
    float i0 = 1.0f/(dn0+1e-6f); outx[q      ] = fx + 0.6f*nx0*i0; outy[q      ] = (float)(ybase  ) + 0.6f*ny0*i0;
    float i1 = 1.0f/(dn1+1e-6f); outx[q +   W] = fx + 0.6f*nx1*i1; outy[q +   W] = (float)(ybase+1) + 0.6f*ny1*i1;
    float i2 = 1.0f/(dn2+1e-6f); outx[q + 2*W] = fx + 0.6f*nx2*i2; outy[q + 2*W] = (float)(ybase+2) + 0.6f*ny2*i2;
    float i3 = 1.0f/(dn3+1e-6f); outx[q + 3*W] = fx + 0.6f*nx3*i3; outy[q + 3*W] = (float)(ybase+3) + 0.6f*ny3*i3;
}

extern "C" void kernel_launch(void* const* d_in, const int* in_sizes, int n_in,
                              void* d_out, int out_size) {
    const float* src = (const float*)d_in[0];
    const float* dst = (const float*)d_in[1];
    const int*   xx  = (const int*)d_in[2];
    const int*   yy  = (const int*)d_in[3];
    int K = in_sizes[2];
    float* out = (float*)d_out;

    // 4 launches per call -> ncu (-s 5 -c 1) lands on k_scan, finally profiling the seed side
    k_nop<<<1, 32>>>();

    dim3 g1(NPIX/256, BB);
    k_scan<<<g1, 256>>>(src);

    dim3 g2(52, BB);
    k_search<<<g2, 256>>>(src, dst, xx, yy, K);

    dim3 g3(TX_N, TY_N, BB);
    k_diffuse<<<g3, 256>>>(out);
}

// round 12
// speedup vs baseline: 2.0275x; 2.0275x over previous
#include <cuda_runtime.h>
#include <cuda_bf16.h>

#define BB 2
#define H 256
#define W 832
#define NPIX (H*W)

#define TS 32
#define HALO 10
#define TY_N (H/TS)          // 8
#define TX_N (W/TS)          // 26
#define NTILE (TY_N*TX_N)    // 208 per batch
#define TCAP 352             // >= 18*18 = 324 (kept points pairwise Chebyshev >= 3 in 52x52 halo)

// per-tile binned active-point lists (zero-initialized at module load; k_diffuse re-zeroes counts)
__device__ int    g_tcnt[BB*NTILE];
__device__ int    g_tpos[BB*NTILE*TCAP];     // (i<<16)|j
__device__ float2 g_tdxy[BB*NTILE*TCAP];
__device__ float  g_wk[441];                 // weight LUT, written by k_seed block (0,0,0) each launch

// on-demand orientation: circular 3x3 box blur + edge-clamped np.gradient -> (cos, sin) of atan2
__device__ __forceinline__ void orient(const float* __restrict__ m, int i, int j,
                                       float& cs, float& ss) {
    float patch[5][5];
#pragma unroll
    for (int r = 0; r < 5; r++) {
        int ii = i + r - 2; ii += (ii < 0) ? H : 0; ii -= (ii >= H) ? H : 0;
#pragma unroll
        for (int c = 0; c < 5; c++) {
            int jj = j + c - 2; jj += (jj < 0) ? W : 0; jj -= (jj >= W) ? W : 0;
            patch[r][c] = m[ii*W + jj];
        }
    }
#define BLUR_AT(di, dj) (patch[1+di][1+dj] + patch[1+di][2+dj] + patch[1+di][3+dj] \
                       + patch[2+di][1+dj] + patch[2+di][2+dj] + patch[2+di][3+dj] \
                       + patch[3+di][1+dj] + patch[3+di][2+dj] + patch[3+di][3+dj])
    float byp = BLUR_AT(1, 0), bym = BLUR_AT(-1, 0), bc = BLUR_AT(0, 0);
    float bxp = BLUR_AT(0, 1), bxm = BLUR_AT(0, -1);
#undef BLUR_AT
    float gyv = (i == 0) ? (byp - bc) : (i == H-1) ? (bc - bym) : 0.5f * (byp - bym);
    float gxv = (j == 0) ? (bxp - bc) : (j == W-1) ? (bc - bxm) : 0.5f * (bxp - bxm);
    float r = sqrtf(gxv*gxv + gyv*gyv);
    if (r > 0.f) { cs = gxv / r; ss = gyv / r; }
    else         { cs = 1.f;     ss = 0.f;     }   // atan2(0,0)=0
}

// ---------------- K1: fused sparsify (smem-staged) + correspondence search + tile binning ----------------
#define STY 8
#define STX 32
__global__ void __launch_bounds__(STY*STX) k_seed(const float* __restrict__ src,
                                                  const float* __restrict__ dst,
                                                  const int* __restrict__ xx,
                                                  const int* __restrict__ yy, int K) {
    __shared__ float s_in[12][36];   // 8x32 tile + 2-halo, 0-filled outside image
    __shared__ int s_pos[48];
    __shared__ int s_cnt;

    int b = blockIdx.z;
    int gy0 = blockIdx.y * STY, gx0 = blockIdx.x * STX;
    int tid = threadIdx.y * STX + threadIdx.x;
    const float* S = src + b*NPIX;
    const float* D = dst + b*NPIX;

    // block (0,0,0): fill the global weight LUT (input-independent, identical every launch).
    if (blockIdx.x == 0 && blockIdx.y == 0 && blockIdx.z == 0) {
        for (int h = tid; h < 441; h += STY*STX) {
            int dy = h / 21 - 10, dx = h % 21 - 10;
            g_wk[h] = expf(-sqrtf((float)(dx*dx + dy*dy)) * 0.2f);
        }
    }

    if (tid == 0) s_cnt = 0;

    // stage 12x36 patch, 2 coalesced rounds, zero-fill outside image
#pragma unroll
    for (int rr = 0; rr < 2; rr++) {
        int h = rr * 256 + tid;
        if (h < 12*36) {
            int r = h / 36, c = h - r*36;
            int gi = gy0 - 2 + r, gj = gx0 - 2 + c;
            float v = (gi >= 0 && gi < H && gj >= 0 && gj < W) ? S[gi*W + gj] : 0.f;
            s_in[r][c] = v;
        }
    }
    __syncthreads();

    // phase 1: keep-test. q < p with q = p + a*W + c reduces to raster-precedence:
    // only offsets (a<0) or (a==0 && c<0) can disqualify. OOB staged as 0 -> auto-excluded.
    int ty = threadIdx.y, tx = threadIdx.x;
    if (s_in[ty+2][tx+2] > 0.5f) {
        float mx = 0.f;
#pragma unroll
        for (int c = 0; c < 5; c++) mx = fmaxf(mx, s_in[ty  ][tx+c]);   // a = -2
#pragma unroll
        for (int c = 0; c < 5; c++) mx = fmaxf(mx, s_in[ty+1][tx+c]);   // a = -1
        mx = fmaxf(mx, s_in[ty+2][tx]);                                  // a = 0, c = -2
        mx = fmaxf(mx, s_in[ty+2][tx+1]);                                // a = 0, c = -1
        if (mx < 0.5f) {
            int idx = atomicAdd(&s_cnt, 1);
            s_pos[idx] = (gy0 + ty)*W + (gx0 + tx);
        }
    }
    __syncthreads();
    int n = s_cnt;

    // phase 2: warp per kept point, K offsets over lanes
    int warp = tid >> 5, lane = tid & 31;
    for (int pt = warp; pt < n; pt += STY*STX/32) {
        int pp = s_pos[pt];
        int pi = pp / W, pj = pp - (pp / W) * W;
        float cs, ssv;
        orient(S, pi, pj, cs, ssv);   // uniform addresses across warp -> broadcast loads
        float best = 1e9f; int bk = 0x7fffffff;
        for (int k = lane; k < K; k += 32) {
            int ox = xx[k], oy = yy[k];
            int ii = pi + oy, jj = pj + ox;
            if (ii >= 0 && ii < H && jj >= 0 && jj < W) {
                int q = ii*W + jj;
                if (D[q] > 0.5f) {
                    float cd, sd;
                    orient(D, ii, jj, cd, sd);   // rare (~2 hits/point)
                    float ang = 1.0f - (cs*cd + ssv*sd);
                    float sc = 20.0f * sqrtf((float)(ox*ox + oy*oy)) + 10.5f * ang;
                    if (sc < best) { best = sc; bk = k; }
                }
            }
        }
        // warp lexicographic (score, k) min -> global first-index-of-min (argmin semantics)
#pragma unroll
        for (int o = 16; o; o >>= 1) {
            float s2 = __shfl_xor_sync(0xffffffffu, best, o);
            int   k2 = __shfl_xor_sync(0xffffffffu, bk, o);
            if (s2 < best || (s2 == best && k2 < bk)) { best = s2; bk = k2; }
        }
        if (lane == 0 && best < 5e8f) {
            float2 dxy = make_float2((float)xx[bk], (float)yy[bk]);
            int pos = (pi << 16) | pj;
            // bin into every 32x32 output tile whose 52x52 halo contains (pi,pj)
            int tylo = (pi <= 41) ? 0 : ((pi - 41 + 31) >> 5);
            int tyhi = min(TY_N - 1, (pi + 10) >> 5);
            int txlo = (pj <= 41) ? 0 : ((pj - 41 + 31) >> 5);
            int txhi = min(TX_N - 1, (pj + 10) >> 5);
            for (int ty2 = tylo; ty2 <= tyhi; ty2++)
                for (int tx2 = txlo; tx2 <= txhi; tx2++) {
                    int tile = (b * TY_N + ty2) * TX_N + tx2;
                    int idx = atomicAdd(&g_tcnt[tile], 1);
                    if (idx < TCAP) {
                        g_tpos[tile*TCAP + idx] = pos;
                        g_tdxy[tile*TCAP + idx] = dxy;
                    }
                }
        }
    }
}

// ---------------- K2: sparse diffusion; 4 rows per thread, warp-uniform row-band skip ----------------
__global__ void __launch_bounds__(256) k_diffuse(float* __restrict__ out) {
    __shared__ float  s_wk[441];
    __shared__ int    s_pos[TCAP];
    __shared__ float2 s_dxy[TCAP];

    int bb  = blockIdx.z;
    int tid = threadIdx.x;
    int tile = (bb * TY_N + blockIdx.y) * TX_N + blockIdx.x;

    // LUT from global (written by k_seed) -- no MUFU here
    s_wk[tid] = g_wk[tid < 441 ? tid : 440];
    if (tid + 256 < 441) s_wk[tid + 256] = g_wk[tid + 256];

    int m = min(g_tcnt[tile], TCAP);
    for (int h = tid; h < m; h += 256) {
        s_pos[h] = g_tpos[tile*TCAP + h];
        s_dxy[h] = g_tdxy[tile*TCAP + h];
    }
    if (tid == 0) g_tcnt[tile] = 0;   // self-reset: next launch starts from zero, no memset node
    __syncthreads();

    int w = tid >> 5, lane = tid & 31;
    int ox = blockIdx.x * TS + lane;
    int ybase = blockIdx.y * TS + 4*w;   // this thread owns rows ybase..ybase+3, column ox

    float nx0=0.f,ny0=0.f,dn0=0.f, nx1=0.f,ny1=0.f,dn1=0.f;
    float nx2=0.f,ny2=0.f,dn2=0.f, nx3=0.f,ny3=0.f,dn3=0.f;

    for (int pI = 0; pI < m; pI++) {
        int pos = s_pos[pI];
        int dyb = (pos >> 16) - ybase + HALO;      // warp-uniform
        if ((unsigned)dyb > 23u) continue;         // uniform skip of ~55% of entries
        int ddx = (pos & 0xffff) - ox + HALO;
        if ((unsigned)ddx <= 20u) {
            float2 d = s_dxy[pI];
            int base = dyb * 21 + ddx;
            if ((unsigned) dyb      <= 20u) { float wv = s_wk[base];      nx0 += wv*d.x; ny0 += wv*d.y; dn0 += wv; }
            if ((unsigned)(dyb - 1) <= 20u) { float wv = s_wk[base - 21]; nx1 += wv*d.x; ny1 += wv*d.y; dn1 += wv; }
            if ((unsigned)(dyb - 2) <= 20u) { float wv = s_wk[base - 42]; nx2 += wv*d.x; ny2 += wv*d.y; dn2 += wv; }
            if ((unsigned)(dyb - 3) <= 20u) { float wv = s_wk[base - 63]; nx3 += wv*d.x; ny3 += wv*d.y; dn3 += wv; }
        }
    }

    float* outx = out + (bb*2 + 0)*NPIX;
    float* outy = out + (bb*2 + 1)*NPIX;
    int q = ybase * W + ox;
    float fx = (float)ox;
    float i0 = 1.0f/(dn0+1e-6f); outx[q      ] = fx + 0.6f*nx0*i0; outy[q      ] = (float)(ybase  ) + 0.6f*ny0*i0;
    float i1 = 1.0f/(dn1+1e-6f); outx[q +   W] = fx + 0.6f*nx1*i1; outy[q +   W] = (float)(ybase+1) + 0.6f*ny1*i1;
    float i2 = 1.0f/(dn2+1e-6f); outx[q + 2*W] = fx + 0.6f*nx2*i2; outy[q + 2*W] = (float)(ybase+2) + 0.6f*ny2*i2;
    float i3 = 1.0f/(dn3+1e-6f); outx[q + 3*W] = fx + 0.6f*nx3*i3; outy[q + 3*W] = (float)(ybase+3) + 0.6f*ny3*i3;
}

extern "C" void kernel_launch(void* const* d_in, const int* in_sizes, int n_in,
                              void* d_out, int out_size) {
    const float* src = (const float*)d_in[0];
    const float* dst = (const float*)d_in[1];
    const int*   xx  = (const int*)d_in[2];
    const int*   yy  = (const int*)d_in[3];
    int K = in_sizes[2];
    float* out = (float*)d_out;

    dim3 gs(W/STX, H/STY, BB), ts(STX, STY);
    k_seed<<<gs, ts>>>(src, dst, xx, yy, K);

    dim3 gd(TX_N, TY_N, BB);
    k_diffuse<<<gd, 256>>>(out);
}